// round 8
// baseline (speedup 1.0000x reference)
#include <cuda_runtime.h>

#define FULLMASK 0xffffffffu
#define ITERS 4   // points per warp; CTA covers 32 points

// ---- weights in constant memory ----
__constant__ float cW1[7 * 32];
__constant__ float cB1[32];
__constant__ float cB2[32];
__constant__ float cW3[32];
__constant__ float cB3[1];

// ---- packed per-point data: [pos.xyz, stddev][norm.xyz, 0] ----
__device__ float4 g_packed[2 * 50048];

__global__ __launch_bounds__(256) void pack_kernel(
    const float* __restrict__ pos,
    const float* __restrict__ normals,
    const float* __restrict__ stddev,
    int N)
{
    int i = blockIdx.x * 256 + threadIdx.x;
    if (i >= N) return;
    float4 a, b;
    a.x = pos[3*i+0]; a.y = pos[3*i+1]; a.z = pos[3*i+2]; a.w = stddev[i];
    b.x = normals[3*i+0]; b.y = normals[3*i+1]; b.z = normals[3*i+2]; b.w = 0.0f;
    g_packed[2*i+0] = a;
    g_packed[2*i+1] = b;
}

__device__ __forceinline__ unsigned f2tf32(float f) {
    unsigned r; asm("cvt.rna.tf32.f32 %0, %1;" : "=r"(r) : "f"(f)); return r;
}
__device__ __forceinline__ void mma8(float& d0, float& d1, float& d2, float& d3,
                                     unsigned a0, unsigned a1, unsigned a2, unsigned a3,
                                     unsigned b0, unsigned b1) {
    asm volatile(
        "mma.sync.aligned.m16n8k8.row.col.f32.tf32.tf32.f32 "
        "{%0,%1,%2,%3}, {%4,%5,%6,%7}, {%8,%9}, {%0,%1,%2,%3};"
        : "+f"(d0), "+f"(d1), "+f"(d2), "+f"(d3)
        : "r"(a0), "r"(a1), "r"(a2), "r"(a3), "r"(b0), "r"(b1));
}

__global__ __launch_bounds__(256, 3) void normal_est_kernel(
    const float* __restrict__ old_w,    // N*32
    const int*   __restrict__ dense_l,  // N*32
    const float* __restrict__ W2g,      // (64,32)
    float* __restrict__ out_normals,
    float* __restrict__ out_weights,
    int N)
{
    __shared__ __align__(16) unsigned sHu[8][32][36];  // per-warp h rows (tf32 bits)
    __shared__            unsigned    sW2f[32][33];    // W2 rows 0..31 tf32 (pad 33: conflict-free)
    __shared__ __align__(16) float    sW2bT[32][36];   // [j][m] = W2[32+m][j]
    __shared__ __align__(16) float    sG[8][32];       // g; reused for wgt redistribution
    __shared__ __align__(8)  float    sGw[8][32];
    __shared__            float       sW3s[32];

    const int tid  = threadIdx.x;
    const int lane = tid & 31;
    const int warp = tid >> 5;
    const int lp   = lane & 3;      // quad-lane
    const int lq   = lane >> 2;     // quad-row

    for (int idx = tid; idx < 1024; idx += 256) {
        int m = idx >> 5, j = idx & 31;
        sW2bT[j][m] = W2g[(32 + m) * 32 + j];
    }
    for (int idx = tid; idx < 1024; idx += 256) {
        int m = idx >> 5, j = idx & 31;
        sW2f[m][j] = f2tf32(W2g[m * 32 + j]);
    }
    if (tid < 32) sW3s[tid] = cW3[tid];
    __syncthreads();

    // ---- B fragments cached in registers ONCE (constant across all points) ----
    unsigned bf0[16], bf1[16];
#pragma unroll
    for (int kt = 0; kt < 4; ++kt)
#pragma unroll
        for (int nt = 0; nt < 4; ++nt) {
            bf0[kt*4+nt] = sW2f[kt*8 + lp    ][nt*8 + lq];
            bf1[kt*4+nt] = sW2f[kt*8 + lp + 4][nt*8 + lq];
        }

    for (int t = 0; t < ITERS; ++t) {
        const int i = blockIdx.x * (8 * ITERS) + t * 8 + warp;
        if (i >= N) continue;

        // ---- gather ----
        const int nb = dense_l[i * 32 + lane];
        const float4 ci = g_packed[2*i+0];
        const float4 ni = g_packed[2*i+1];
        const float4 cj = g_packed[2*nb+0];
        const float4 nj = g_packed[2*nb+1];

        const float dcx = cj.x - ci.x, dcy = cj.y - ci.y, dcz = cj.z - ci.z;
        const float invsd = 1.0f / ci.w;
        const float dx = dcx * invsd, dy = dcy * invsd, dz = dcz * invsd;
        const float wo = old_w[i * 32 + lane];
        const float f4 = fabsf(dx*ni.x + dy*ni.y + dz*ni.z);
        const float f5 = fabsf(dx*nj.x + dy*nj.y + dz*nj.z);
        const float f6 = fabsf(ni.x*nj.x + ni.y*nj.y + ni.z*nj.z);
        float f[7];
        f[0] = dx; f[1] = dy; f[2] = dz; f[3] = wo; f[4] = f4; f[5] = f5; f[6] = f6;

        // ---- layer 1 in two 16-wide halves (caps live registers) ----
#pragma unroll
        for (int jh = 0; jh < 2; ++jh) {
            float h[16];
#pragma unroll
            for (int k = 0; k < 16; k += 4) {
                const float4 bv = *(const float4*)&cB1[jh*16 + k];
                h[k+0] = bv.x; h[k+1] = bv.y; h[k+2] = bv.z; h[k+3] = bv.w;
            }
#pragma unroll
            for (int in = 0; in < 7; ++in) {
                const float fv = f[in];
#pragma unroll
                for (int k = 0; k < 16; k += 4) {
                    const float4 wv = *(const float4*)&cW1[in*32 + jh*16 + k];
                    h[k+0] = fmaf(fv, wv.x, h[k+0]);
                    h[k+1] = fmaf(fv, wv.y, h[k+1]);
                    h[k+2] = fmaf(fv, wv.z, h[k+2]);
                    h[k+3] = fmaf(fv, wv.w, h[k+3]);
                }
            }
            unsigned* hrow = &sHu[warp][lane][jh*16];
#pragma unroll
            for (int q = 0; q < 4; ++q) {
                uint4 v;
                v.x = f2tf32(fmaxf(h[4*q+0], 0.0f));
                v.y = f2tf32(fmaxf(h[4*q+1], 0.0f));
                v.z = f2tf32(fmaxf(h[4*q+2], 0.0f));
                v.w = f2tf32(fmaxf(h[4*q+3], 0.0f));
                ((uint4*)hrow)[q] = v;
            }
        }
        __syncwarp();

        // ---- segment max: lane j maxes column j over 32 rows (tf32 values) ----
        float g = __uint_as_float(sHu[warp][0][lane]);
#pragma unroll
        for (int e = 1; e < 32; ++e)
            g = fmaxf(g, __uint_as_float(sHu[warp][e][lane]));
        sG[warp][lane] = g;
        __syncwarp();

        // ---- gw = b2 + g @ W2[32:64] (fp32, once per point) ----
        float gw = cB2[lane];
        {
            const float4* grow = (const float4*)&sG[warp][0];
            const float4* wrow = (const float4*)&sW2bT[lane][0];
#pragma unroll
            for (int q = 0; q < 8; ++q) {
                const float4 gv = grow[q], wv = wrow[q];
                gw = fmaf(gv.x, wv.x, gw); gw = fmaf(gv.y, wv.y, gw);
                gw = fmaf(gv.z, wv.z, gw); gw = fmaf(gv.w, wv.w, gw);
            }
        }
        sGw[warp][lane] = gw;
        __syncwarp();

        // ---- layer 2 on tensor pipe (B cached in registers) ----
        float s3p[4] = {0.0f, 0.0f, 0.0f, 0.0f};
#pragma unroll
        for (int mt = 0; mt < 2; ++mt) {
            unsigned a[16];
#pragma unroll
            for (int kt = 0; kt < 4; ++kt) {
                a[kt*4+0] = sHu[warp][mt*16 + lq    ][kt*8 + lp    ];
                a[kt*4+1] = sHu[warp][mt*16 + lq + 8][kt*8 + lp    ];
                a[kt*4+2] = sHu[warp][mt*16 + lq    ][kt*8 + lp + 4];
                a[kt*4+3] = sHu[warp][mt*16 + lq + 8][kt*8 + lp + 4];
            }
#pragma unroll
            for (int nt = 0; nt < 4; ++nt) {
                float d0 = 0.0f, d1 = 0.0f, d2 = 0.0f, d3 = 0.0f;
#pragma unroll
                for (int kt = 0; kt < 4; ++kt)
                    mma8(d0, d1, d2, d3,
                         a[kt*4+0], a[kt*4+1], a[kt*4+2], a[kt*4+3],
                         bf0[kt*4+nt], bf1[kt*4+nt]);
                const int c0 = nt*8 + 2*lp;
                const float2 gv = *(const float2*)&sGw[warp][c0];
                const float2 wv = *(const float2*)&sW3s[c0];
                s3p[mt*2+0] = fmaf(fmaxf(d0 + gv.x, 0.0f), wv.x, s3p[mt*2+0]);
                s3p[mt*2+0] = fmaf(fmaxf(d1 + gv.y, 0.0f), wv.y, s3p[mt*2+0]);
                s3p[mt*2+1] = fmaf(fmaxf(d2 + gv.x, 0.0f), wv.x, s3p[mt*2+1]);
                s3p[mt*2+1] = fmaf(fmaxf(d3 + gv.y, 0.0f), wv.y, s3p[mt*2+1]);
            }
        }
#pragma unroll
        for (int k = 0; k < 4; ++k) {
            s3p[k] += __shfl_xor_sync(FULLMASK, s3p[k], 1);
            s3p[k] += __shfl_xor_sync(FULLMASK, s3p[k], 2);
        }
        float wr[4];
#pragma unroll
        for (int k = 0; k < 4; ++k)
            wr[k] = 1.0f / (1.0f + __expf(-(s3p[k] + cB3[0])));
        if (lp == 0) {
            sG[warp][lq     ] = wr[0];
            sG[warp][lq +  8] = wr[1];
            sG[warp][lq + 16] = wr[2];
            sG[warp][lq + 24] = wr[3];
        }
        __syncwarp();
        const float wgt = sG[warp][lane];

        out_weights[i * 32 + lane] = wgt;

        // ---- weighted covariance (unscaled dc), 6-term butterfly ----
        float cxx = wgt*dcx*dcx, cxy = wgt*dcx*dcy, cxz = wgt*dcx*dcz;
        float cyy = wgt*dcy*dcy, cyz = wgt*dcy*dcz, czz = wgt*dcz*dcz;
#pragma unroll
        for (int s = 16; s > 0; s >>= 1) {
            cxx += __shfl_xor_sync(FULLMASK, cxx, s);
            cxy += __shfl_xor_sync(FULLMASK, cxy, s);
            cxz += __shfl_xor_sync(FULLMASK, cxz, s);
            cyy += __shfl_xor_sync(FULLMASK, cyy, s);
            cyz += __shfl_xor_sync(FULLMASK, cyz, s);
            czz += __shfl_xor_sync(FULLMASK, czz, s);
        }

        if (lane == 0) {
            const float a00 = cxx + 1e-8f, a11 = cyy + 1e-8f, a22 = czz + 1e-8f;
            const float a01 = cxy, a02 = cxz, a12 = cyz;

            const float q = (a00 + a11 + a22) / 3.0f;
            const float b00 = a00 - q, b11 = a11 - q, b22 = a22 - q;
            const float ss = b00*b00 + b11*b11 + b22*b22
                           + 2.0f*(a01*a01 + a02*a02 + a12*a12);
            const float p = sqrtf(ss / 6.0f) + 1e-20f;

            const float B00 = b00/p, B11 = b11/p, B22 = b22/p;
            const float B01 = a01/p, B02 = a02/p, B12 = a12/p;
            const float det = B00*(B11*B22 - B12*B12)
                            - B01*(B01*B22 - B12*B02)
                            + B02*(B01*B12 - B11*B02);
            float r = det / 2.0f;
            r = fminf(fmaxf(r, -1.0f + 1e-7f), 1.0f - 1e-7f);
            const float phi = acosf(r) / 3.0f;
            const float e1 = q + 2.0f*p*cosf(phi);
            const float e3 = q + 2.0f*p*cosf(phi + 2.0943951023931953f);
            const float e2 = 3.0f*q - e1 - e3;

            float lam = e1, ab = fabsf(e1);
            if (fabsf(e2) < ab) { lam = e2; ab = fabsf(e2); }
            if (fabsf(e3) < ab) { lam = e3; }

            const float m00 = a00 - lam, m11 = a11 - lam, m22 = a22 - lam;
            const float c0x = a01*a12 - a02*m11;
            const float c0y = a02*a01 - m00*a12;
            const float c0z = m00*m11 - a01*a01;
            const float c1x = m11*m22 - a12*a12;
            const float c1y = a12*a02 - a01*m22;
            const float c1z = a01*a12 - m11*a02;
            const float c2x = a12*a02 - m22*a01;
            const float c2y = m22*m00 - a02*a02;
            const float c2z = a02*a01 - a12*m00;

            const float n0 = sqrtf(c0x*c0x + c0y*c0y + c0z*c0z);
            const float n1 = sqrtf(c1x*c1x + c1y*c1y + c1z*c1z);
            const float n2 = sqrtf(c2x*c2x + c2y*c2y + c2z*c2z);

            float vx = c0x, vy = c0y, vz = c0z, bn = n0;
            if (n1 > bn) { vx = c1x; vy = c1y; vz = c1z; bn = n1; }
            if (n2 > bn) { vx = c2x; vy = c2y; vz = c2z; }

            const float nv = sqrtf(vx*vx + vy*vy + vz*vz) + 1e-12f;
            out_normals[3*i+0] = vx / nv;
            out_normals[3*i+1] = vy / nv;
            out_normals[3*i+2] = vz / nv;
        }
        __syncwarp();
    }
}

extern "C" void kernel_launch(void* const* d_in, const int* in_sizes, int n_in,
                              void* d_out, int out_size)
{
    const float* old_w   = (const float*)d_in[0];
    const float* pos     = (const float*)d_in[1];
    const float* normals = (const float*)d_in[3];
    const int*   dense_l = (const int*)d_in[5];
    const float* stddev  = (const float*)d_in[6];
    const float* W1      = (const float*)d_in[7];
    const float* b1      = (const float*)d_in[8];
    const float* W2      = (const float*)d_in[9];
    const float* b2      = (const float*)d_in[10];
    const float* W3      = (const float*)d_in[11];
    const float* b3      = (const float*)d_in[12];

    const int N = in_sizes[1] / 3;

    cudaMemcpyToSymbolAsync(cW1, W1, 7 * 32 * sizeof(float), 0, cudaMemcpyDeviceToDevice);
    cudaMemcpyToSymbolAsync(cB1, b1, 32 * sizeof(float),     0, cudaMemcpyDeviceToDevice);
    cudaMemcpyToSymbolAsync(cB2, b2, 32 * sizeof(float),     0, cudaMemcpyDeviceToDevice);
    cudaMemcpyToSymbolAsync(cW3, W3, 32 * sizeof(float),     0, cudaMemcpyDeviceToDevice);
    cudaMemcpyToSymbolAsync(cB3, b3, sizeof(float),          0, cudaMemcpyDeviceToDevice);

    float* out         = (float*)d_out;
    float* out_normals = out;
    float* out_weights = out + (size_t)N * 3;

    pack_kernel<<<(N + 255) / 256, 256>>>(pos, normals, stddev, N);

    const int pts_per_cta = 8 * ITERS;
    dim3 block(256);
    dim3 grid((N + pts_per_cta - 1) / pts_per_cta);
    normal_est_kernel<<<grid, block>>>(old_w, dense_l, W2,
                                       out_normals, out_weights, N);
}

// round 9
// speedup vs baseline: 1.0831x; 1.0831x over previous
#include <cuda_runtime.h>

#define FULLMASK 0xffffffffu
#define ITERS 4   // points per warp; CTA covers 32 points

// ---- weights in constant memory ----
__constant__ float cW1[7 * 32];
__constant__ float cB1[32];
__constant__ float cB2[32];
__constant__ float cW3[32];
__constant__ float cB3[1];

// ---- packed per-point data: [pos.xyz, stddev][norm.xyz, 0] ----
__device__ float4 g_packed[2 * 50048];

__global__ __launch_bounds__(256) void pack_kernel(
    const float* __restrict__ pos,
    const float* __restrict__ normals,
    const float* __restrict__ stddev,
    int N)
{
    int i = blockIdx.x * 256 + threadIdx.x;
    if (i >= N) return;
    float4 a, b;
    a.x = pos[3*i+0]; a.y = pos[3*i+1]; a.z = pos[3*i+2]; a.w = stddev[i];
    b.x = normals[3*i+0]; b.y = normals[3*i+1]; b.z = normals[3*i+2]; b.w = 0.0f;
    g_packed[2*i+0] = a;
    g_packed[2*i+1] = b;
}

__device__ __forceinline__ unsigned f2tf32(float f) {
    unsigned r; asm("cvt.rna.tf32.f32 %0, %1;" : "=r"(r) : "f"(f)); return r;
}
__device__ __forceinline__ void mma8(float& d0, float& d1, float& d2, float& d3,
                                     unsigned a0, unsigned a1, unsigned a2, unsigned a3,
                                     unsigned b0, unsigned b1) {
    asm volatile(
        "mma.sync.aligned.m16n8k8.row.col.f32.tf32.tf32.f32 "
        "{%0,%1,%2,%3}, {%4,%5,%6,%7}, {%8,%9}, {%0,%1,%2,%3};"
        : "+f"(d0), "+f"(d1), "+f"(d2), "+f"(d3)
        : "r"(a0), "r"(a1), "r"(a2), "r"(a3), "r"(b0), "r"(b1));
}

__global__ __launch_bounds__(256, 4) void normal_est_kernel(
    const float* __restrict__ old_w,    // N*32
    const int*   __restrict__ dense_l,  // N*32
    const float* __restrict__ W2g,      // (64,32)
    float* __restrict__ out_normals,
    float* __restrict__ out_weights,
    int N)
{
    __shared__ __align__(16) unsigned sHu[8][32][36];  // per-warp h rows (tf32 bits)
    __shared__            unsigned    sB0[16][32];     // B frags (row lp),  [kt*4+nt][lane]
    __shared__            unsigned    sB1[16][32];     // B frags (row lp+4)
    __shared__ __align__(16) float    sW2bT[32][36];   // [j][m] = W2[32+m][j]
    __shared__ __align__(16) float    sG[8][32];       // g; reused for wgt redistribution
    __shared__ __align__(8)  float    sGw[8][32];
    __shared__            float       sW3s[32];
    __shared__            float       sCov[32][8];     // 6 cov sums per CTA point slot

    const int tid  = threadIdx.x;
    const int lane = tid & 31;
    const int warp = tid >> 5;
    const int lp   = lane & 3;      // quad-lane
    const int lq   = lane >> 2;     // quad-row

    for (int idx = tid; idx < 1024; idx += 256) {
        int m = idx >> 5, j = idx & 31;
        sW2bT[j][m] = W2g[(32 + m) * 32 + j];
    }
    // fragment-order B (conflict-free, zero address math at use site)
    for (int idx = tid; idx < 512; idx += 256) {
        const int frag = idx >> 5, l2 = idx & 31;
        const int lp2 = l2 & 3, lq2 = l2 >> 2;
        const int kt = frag >> 2, nt = frag & 3;
        sB0[frag][l2] = f2tf32(W2g[(kt*8 + lp2    ) * 32 + nt*8 + lq2]);
        sB1[frag][l2] = f2tf32(W2g[(kt*8 + lp2 + 4) * 32 + nt*8 + lq2]);
    }
    if (tid < 32) sW3s[tid] = cW3[tid];
    __syncthreads();

    for (int t = 0; t < ITERS; ++t) {
        const int i = blockIdx.x * (8 * ITERS) + t * 8 + warp;
        if (i < N) {

        // ---- gather ----
        const int nb = dense_l[i * 32 + lane];
        const float4 ci = g_packed[2*i+0];
        const float4 ni = g_packed[2*i+1];
        const float4 cj = g_packed[2*nb+0];
        const float4 nj = g_packed[2*nb+1];

        const float dcx = cj.x - ci.x, dcy = cj.y - ci.y, dcz = cj.z - ci.z;
        const float invsd = 1.0f / ci.w;
        const float dx = dcx * invsd, dy = dcy * invsd, dz = dcz * invsd;
        const float wo = old_w[i * 32 + lane];
        const float f4 = fabsf(dx*ni.x + dy*ni.y + dz*ni.z);
        const float f5 = fabsf(dx*nj.x + dy*nj.y + dz*nj.z);
        const float f6 = fabsf(ni.x*nj.x + ni.y*nj.y + ni.z*nj.z);
        float f[7];
        f[0] = dx; f[1] = dy; f[2] = dz; f[3] = wo; f[4] = f4; f[5] = f5; f[6] = f6;

        // ---- layer 1 (constant port), two 16-wide halves ----
#pragma unroll
        for (int jh = 0; jh < 2; ++jh) {
            float h[16];
#pragma unroll
            for (int k = 0; k < 16; k += 4) {
                const float4 bv = *(const float4*)&cB1[jh*16 + k];
                h[k+0] = bv.x; h[k+1] = bv.y; h[k+2] = bv.z; h[k+3] = bv.w;
            }
#pragma unroll
            for (int in = 0; in < 7; ++in) {
                const float fv = f[in];
#pragma unroll
                for (int k = 0; k < 16; k += 4) {
                    const float4 wv = *(const float4*)&cW1[in*32 + jh*16 + k];
                    h[k+0] = fmaf(fv, wv.x, h[k+0]);
                    h[k+1] = fmaf(fv, wv.y, h[k+1]);
                    h[k+2] = fmaf(fv, wv.z, h[k+2]);
                    h[k+3] = fmaf(fv, wv.w, h[k+3]);
                }
            }
            unsigned* hrow = &sHu[warp][lane][jh*16];
#pragma unroll
            for (int q = 0; q < 4; ++q) {
                uint4 v;
                v.x = f2tf32(fmaxf(h[4*q+0], 0.0f));
                v.y = f2tf32(fmaxf(h[4*q+1], 0.0f));
                v.z = f2tf32(fmaxf(h[4*q+2], 0.0f));
                v.w = f2tf32(fmaxf(h[4*q+3], 0.0f));
                ((uint4*)hrow)[q] = v;
            }
        }
        __syncwarp();

        // ---- segment max: lane j maxes column j over 32 rows ----
        float g = __uint_as_float(sHu[warp][0][lane]);
#pragma unroll
        for (int e = 1; e < 32; ++e)
            g = fmaxf(g, __uint_as_float(sHu[warp][e][lane]));
        sG[warp][lane] = g;
        __syncwarp();

        // ---- gw = b2 + g @ W2[32:64] (fp32, once per point) ----
        float gw = cB2[lane];
        {
            const float4* grow = (const float4*)&sG[warp][0];
            const float4* wrow = (const float4*)&sW2bT[lane][0];
#pragma unroll
            for (int q = 0; q < 8; ++q) {
                const float4 gv = grow[q], wv = wrow[q];
                gw = fmaf(gv.x, wv.x, gw); gw = fmaf(gv.y, wv.y, gw);
                gw = fmaf(gv.z, wv.z, gw); gw = fmaf(gv.w, wv.w, gw);
            }
        }
        sGw[warp][lane] = gw;
        __syncwarp();

        // ---- layer 2 on tensor pipe ----
        float s3p[4] = {0.0f, 0.0f, 0.0f, 0.0f};
#pragma unroll
        for (int mt = 0; mt < 2; ++mt) {
            unsigned a[16];
#pragma unroll
            for (int kt = 0; kt < 4; ++kt) {
                a[kt*4+0] = sHu[warp][mt*16 + lq    ][kt*8 + lp    ];
                a[kt*4+1] = sHu[warp][mt*16 + lq + 8][kt*8 + lp    ];
                a[kt*4+2] = sHu[warp][mt*16 + lq    ][kt*8 + lp + 4];
                a[kt*4+3] = sHu[warp][mt*16 + lq + 8][kt*8 + lp + 4];
            }
#pragma unroll
            for (int nt = 0; nt < 4; ++nt) {
                float d0 = 0.0f, d1 = 0.0f, d2 = 0.0f, d3 = 0.0f;
#pragma unroll
                for (int kt = 0; kt < 4; ++kt)
                    mma8(d0, d1, d2, d3,
                         a[kt*4+0], a[kt*4+1], a[kt*4+2], a[kt*4+3],
                         sB0[kt*4+nt][lane], sB1[kt*4+nt][lane]);
                const int c0 = nt*8 + 2*lp;
                const float2 gv = *(const float2*)&sGw[warp][c0];
                const float2 wv = *(const float2*)&sW3s[c0];
                s3p[mt*2+0] = fmaf(fmaxf(d0 + gv.x, 0.0f), wv.x, s3p[mt*2+0]);
                s3p[mt*2+0] = fmaf(fmaxf(d1 + gv.y, 0.0f), wv.y, s3p[mt*2+0]);
                s3p[mt*2+1] = fmaf(fmaxf(d2 + gv.x, 0.0f), wv.x, s3p[mt*2+1]);
                s3p[mt*2+1] = fmaf(fmaxf(d3 + gv.y, 0.0f), wv.y, s3p[mt*2+1]);
            }
        }
#pragma unroll
        for (int k = 0; k < 4; ++k) {
            s3p[k] += __shfl_xor_sync(FULLMASK, s3p[k], 1);
            s3p[k] += __shfl_xor_sync(FULLMASK, s3p[k], 2);
        }
        float wr[4];
#pragma unroll
        for (int k = 0; k < 4; ++k)
            wr[k] = 1.0f / (1.0f + __expf(-(s3p[k] + cB3[0])));
        if (lp == 0) {
            sG[warp][lq     ] = wr[0];
            sG[warp][lq +  8] = wr[1];
            sG[warp][lq + 16] = wr[2];
            sG[warp][lq + 24] = wr[3];
        }
        __syncwarp();
        const float wgt = sG[warp][lane];

        out_weights[i * 32 + lane] = wgt;

        // ---- weighted covariance butterfly; lane 0 stashes sums ----
        float cxx = wgt*dcx*dcx, cxy = wgt*dcx*dcy, cxz = wgt*dcx*dcz;
        float cyy = wgt*dcy*dcy, cyz = wgt*dcy*dcz, czz = wgt*dcz*dcz;
#pragma unroll
        for (int s = 16; s > 0; s >>= 1) {
            cxx += __shfl_xor_sync(FULLMASK, cxx, s);
            cxy += __shfl_xor_sync(FULLMASK, cxy, s);
            cxz += __shfl_xor_sync(FULLMASK, cxz, s);
            cyy += __shfl_xor_sync(FULLMASK, cyy, s);
            cyz += __shfl_xor_sync(FULLMASK, cyz, s);
            czz += __shfl_xor_sync(FULLMASK, czz, s);
        }
        if (lane == 0) {
            const int slot = t * 8 + warp;
            sCov[slot][0] = cxx; sCov[slot][1] = cxy; sCov[slot][2] = cxz;
            sCov[slot][3] = cyy; sCov[slot][4] = cyz; sCov[slot][5] = czz;
        }

        } // i < N
        __syncwarp();
    }

    // ---- batched eigensolve: 32 points of this CTA, lane-parallel on warp 0 ----
    __syncthreads();
    if (warp == 0) {
        const int p = blockIdx.x * 32 + lane;
        if (p < N) {
            const float a00 = sCov[lane][0] + 1e-8f;
            const float a01 = sCov[lane][1];
            const float a02 = sCov[lane][2];
            const float a11 = sCov[lane][3] + 1e-8f;
            const float a12 = sCov[lane][4];
            const float a22 = sCov[lane][5] + 1e-8f;

            const float q = (a00 + a11 + a22) / 3.0f;
            const float b00 = a00 - q, b11 = a11 - q, b22 = a22 - q;
            const float ss = b00*b00 + b11*b11 + b22*b22
                           + 2.0f*(a01*a01 + a02*a02 + a12*a12);
            const float pp = sqrtf(ss / 6.0f) + 1e-20f;

            const float B00 = b00/pp, B11 = b11/pp, B22 = b22/pp;
            const float B01 = a01/pp, B02 = a02/pp, B12 = a12/pp;
            const float det = B00*(B11*B22 - B12*B12)
                            - B01*(B01*B22 - B12*B02)
                            + B02*(B01*B12 - B11*B02);
            float r = det / 2.0f;
            r = fminf(fmaxf(r, -1.0f + 1e-7f), 1.0f - 1e-7f);
            const float phi = acosf(r) / 3.0f;
            const float e1 = q + 2.0f*pp*cosf(phi);
            const float e3 = q + 2.0f*pp*cosf(phi + 2.0943951023931953f);
            const float e2 = 3.0f*q - e1 - e3;

            float lam = e1, ab = fabsf(e1);
            if (fabsf(e2) < ab) { lam = e2; ab = fabsf(e2); }
            if (fabsf(e3) < ab) { lam = e3; }

            const float m00 = a00 - lam, m11 = a11 - lam, m22 = a22 - lam;
            const float c0x = a01*a12 - a02*m11;
            const float c0y = a02*a01 - m00*a12;
            const float c0z = m00*m11 - a01*a01;
            const float c1x = m11*m22 - a12*a12;
            const float c1y = a12*a02 - a01*m22;
            const float c1z = a01*a12 - m11*a02;
            const float c2x = a12*a02 - m22*a01;
            const float c2y = m22*m00 - a02*a02;
            const float c2z = a02*a01 - a12*m00;

            const float n0 = sqrtf(c0x*c0x + c0y*c0y + c0z*c0z);
            const float n1 = sqrtf(c1x*c1x + c1y*c1y + c1z*c1z);
            const float n2 = sqrtf(c2x*c2x + c2y*c2y + c2z*c2z);

            float vx = c0x, vy = c0y, vz = c0z, bn = n0;
            if (n1 > bn) { vx = c1x; vy = c1y; vz = c1z; bn = n1; }
            if (n2 > bn) { vx = c2x; vy = c2y; vz = c2z; }

            const float nv = sqrtf(vx*vx + vy*vy + vz*vz) + 1e-12f;
            out_normals[3*p+0] = vx / nv;
            out_normals[3*p+1] = vy / nv;
            out_normals[3*p+2] = vz / nv;
        }
    }
}

extern "C" void kernel_launch(void* const* d_in, const int* in_sizes, int n_in,
                              void* d_out, int out_size)
{
    const float* old_w   = (const float*)d_in[0];
    const float* pos     = (const float*)d_in[1];
    const float* normals = (const float*)d_in[3];
    const int*   dense_l = (const int*)d_in[5];
    const float* stddev  = (const float*)d_in[6];
    const float* W1      = (const float*)d_in[7];
    const float* b1      = (const float*)d_in[8];
    const float* W2      = (const float*)d_in[9];
    const float* b2      = (const float*)d_in[10];
    const float* W3      = (const float*)d_in[11];
    const float* b3      = (const float*)d_in[12];

    const int N = in_sizes[1] / 3;

    cudaMemcpyToSymbolAsync(cW1, W1, 7 * 32 * sizeof(float), 0, cudaMemcpyDeviceToDevice);
    cudaMemcpyToSymbolAsync(cB1, b1, 32 * sizeof(float),     0, cudaMemcpyDeviceToDevice);
    cudaMemcpyToSymbolAsync(cB2, b2, 32 * sizeof(float),     0, cudaMemcpyDeviceToDevice);
    cudaMemcpyToSymbolAsync(cW3, W3, 32 * sizeof(float),     0, cudaMemcpyDeviceToDevice);
    cudaMemcpyToSymbolAsync(cB3, b3, sizeof(float),          0, cudaMemcpyDeviceToDevice);

    float* out         = (float*)d_out;
    float* out_normals = out;
    float* out_weights = out + (size_t)N * 3;

    pack_kernel<<<(N + 255) / 256, 256>>>(pos, normals, stddev, N);

    const int pts_per_cta = 8 * ITERS;
    dim3 block(256);
    dim3 grid((N + pts_per_cta - 1) / pts_per_cta);
    normal_est_kernel<<<grid, block>>>(old_w, dense_l, W2,
                                       out_normals, out_weights, N);
}

// round 11
// speedup vs baseline: 1.1290x; 1.0423x over previous
#include <cuda_runtime.h>

#define FULLMASK 0xffffffffu
#define ITERS 4   // points per warp; CTA covers 32 points

// ---- weights in constant memory ----
__constant__ float cW1[7 * 32];
__constant__ float cB1[32];
__constant__ float cB2[32];
__constant__ float cW3[32];
__constant__ float cB3[1];

// ---- packed per-point data: one 32B-aligned record = [pos.xyz, stddev][norm.xyz, 0] ----
struct __align__(32) PtData { float4 c; float4 n; };
__device__ PtData g_pt[50048];

__global__ __launch_bounds__(256) void pack_kernel(
    const float* __restrict__ pos,
    const float* __restrict__ normals,
    const float* __restrict__ stddev,
    int N)
{
    int i = blockIdx.x * 256 + threadIdx.x;
    if (i >= N) return;
    float4 a, b;
    a.x = pos[3*i+0]; a.y = pos[3*i+1]; a.z = pos[3*i+2]; a.w = stddev[i];
    b.x = normals[3*i+0]; b.y = normals[3*i+1]; b.z = normals[3*i+2]; b.w = 0.0f;
    g_pt[i].c = a;
    g_pt[i].n = b;
}

// 256-bit global load (sm_100+ base ISA): one instruction, one wavefront set
__device__ __forceinline__ void ldg256(const PtData* p, float4& a, float4& b) {
    asm("ld.global.nc.v8.f32 {%0,%1,%2,%3,%4,%5,%6,%7}, [%8];"
        : "=f"(a.x), "=f"(a.y), "=f"(a.z), "=f"(a.w),
          "=f"(b.x), "=f"(b.y), "=f"(b.z), "=f"(b.w)
        : "l"(p));
}

__device__ __forceinline__ unsigned f2tf32(float f) {
    unsigned r; asm("cvt.rna.tf32.f32 %0, %1;" : "=r"(r) : "f"(f)); return r;
}
__device__ __forceinline__ void mma8(float& d0, float& d1, float& d2, float& d3,
                                     unsigned a0, unsigned a1, unsigned a2, unsigned a3,
                                     unsigned b0, unsigned b1) {
    asm volatile(
        "mma.sync.aligned.m16n8k8.row.col.f32.tf32.tf32.f32 "
        "{%0,%1,%2,%3}, {%4,%5,%6,%7}, {%8,%9}, {%0,%1,%2,%3};"
        : "+f"(d0), "+f"(d1), "+f"(d2), "+f"(d3)
        : "r"(a0), "r"(a1), "r"(a2), "r"(a3), "r"(b0), "r"(b1));
}

__global__ __launch_bounds__(256, 4) void normal_est_kernel(
    const float* __restrict__ old_w,    // N*32
    const int*   __restrict__ dense_l,  // N*32
    const float* __restrict__ W2g,      // (64,32)
    float* __restrict__ out_normals,
    float* __restrict__ out_weights,
    int N)
{
    __shared__ __align__(16) unsigned sHu[8][32][36];  // per-warp h rows (tf32 bits)
    __shared__            unsigned    sB0[16][32];     // B frags (row lp),  [kt*4+nt][lane]
    __shared__            unsigned    sB1[16][32];     // B frags (row lp+4)
    __shared__ __align__(16) float    sW2bT[32][36];   // [j][m] = W2[32+m][j]
    __shared__ __align__(16) float    sG[8][32];       // g; reused for wgt redistribution
    __shared__ __align__(8)  float    sGw[8][32];
    __shared__            float       sW3s[32];
    __shared__            float       sCov[32][8];     // 6 cov sums per CTA point slot

    const int tid  = threadIdx.x;
    const int lane = tid & 31;
    const int warp = tid >> 5;
    const int lp   = lane & 3;      // quad-lane
    const int lq   = lane >> 2;     // quad-row

    for (int idx = tid; idx < 1024; idx += 256) {
        int m = idx >> 5, j = idx & 31;
        sW2bT[j][m] = W2g[(32 + m) * 32 + j];
    }
    // fragment-order B (conflict-free, zero address math at use site)
    for (int idx = tid; idx < 512; idx += 256) {
        const int frag = idx >> 5, l2 = idx & 31;
        const int lp2 = l2 & 3, lq2 = l2 >> 2;
        const int kt = frag >> 2, nt = frag & 3;
        sB0[frag][l2] = f2tf32(W2g[(kt*8 + lp2    ) * 32 + nt*8 + lq2]);
        sB1[frag][l2] = f2tf32(W2g[(kt*8 + lp2 + 4) * 32 + nt*8 + lq2]);
    }
    if (tid < 32) sW3s[tid] = cW3[tid];
    __syncthreads();

    for (int t = 0; t < ITERS; ++t) {
        const int i = blockIdx.x * (8 * ITERS) + t * 8 + warp;
        if (i < N) {

        // ---- gather: ONE 256-bit load per neighbor record ----
        const int nb = dense_l[i * 32 + lane];
        float4 ci, ni, cj, nj;
        ldg256(&g_pt[i],  ci, ni);   // broadcast
        ldg256(&g_pt[nb], cj, nj);   // scattered

        const float dcx = cj.x - ci.x, dcy = cj.y - ci.y, dcz = cj.z - ci.z;
        const float invsd = 1.0f / ci.w;
        const float dx = dcx * invsd, dy = dcy * invsd, dz = dcz * invsd;
        const float wo = old_w[i * 32 + lane];
        const float f4 = fabsf(dx*ni.x + dy*ni.y + dz*ni.z);
        const float f5 = fabsf(dx*nj.x + dy*nj.y + dz*nj.z);
        const float f6 = fabsf(ni.x*nj.x + ni.y*nj.y + ni.z*nj.z);
        float f[7];
        f[0] = dx; f[1] = dy; f[2] = dz; f[3] = wo; f[4] = f4; f[5] = f5; f[6] = f6;

        // ---- layer 1 (constant port), two 16-wide halves ----
#pragma unroll
        for (int jh = 0; jh < 2; ++jh) {
            float h[16];
#pragma unroll
            for (int k = 0; k < 16; k += 4) {
                const float4 bv = *(const float4*)&cB1[jh*16 + k];
                h[k+0] = bv.x; h[k+1] = bv.y; h[k+2] = bv.z; h[k+3] = bv.w;
            }
#pragma unroll
            for (int in = 0; in < 7; ++in) {
                const float fv = f[in];
#pragma unroll
                for (int k = 0; k < 16; k += 4) {
                    const float4 wv = *(const float4*)&cW1[in*32 + jh*16 + k];
                    h[k+0] = fmaf(fv, wv.x, h[k+0]);
                    h[k+1] = fmaf(fv, wv.y, h[k+1]);
                    h[k+2] = fmaf(fv, wv.z, h[k+2]);
                    h[k+3] = fmaf(fv, wv.w, h[k+3]);
                }
            }
            unsigned* hrow = &sHu[warp][lane][jh*16];
#pragma unroll
            for (int q = 0; q < 4; ++q) {
                uint4 v;
                v.x = f2tf32(fmaxf(h[4*q+0], 0.0f));
                v.y = f2tf32(fmaxf(h[4*q+1], 0.0f));
                v.z = f2tf32(fmaxf(h[4*q+2], 0.0f));
                v.w = f2tf32(fmaxf(h[4*q+3], 0.0f));
                ((uint4*)hrow)[q] = v;
            }
        }
        __syncwarp();

        // ---- segment max: lane j maxes column j over 32 rows ----
        float g = __uint_as_float(sHu[warp][0][lane]);
#pragma unroll
        for (int e = 1; e < 32; ++e)
            g = fmaxf(g, __uint_as_float(sHu[warp][e][lane]));
        sG[warp][lane] = g;
        __syncwarp();

        // ---- gw = b2 + g @ W2[32:64] (fp32, once per point) ----
        float gw = cB2[lane];
        {
            const float4* grow = (const float4*)&sG[warp][0];
            const float4* wrow = (const float4*)&sW2bT[lane][0];
#pragma unroll
            for (int q = 0; q < 8; ++q) {
                const float4 gv = grow[q], wv = wrow[q];
                gw = fmaf(gv.x, wv.x, gw); gw = fmaf(gv.y, wv.y, gw);
                gw = fmaf(gv.z, wv.z, gw); gw = fmaf(gv.w, wv.w, gw);
            }
        }
        sGw[warp][lane] = gw;
        __syncwarp();

        // ---- layer 2 on tensor pipe ----
        float s3p[4] = {0.0f, 0.0f, 0.0f, 0.0f};
#pragma unroll
        for (int mt = 0; mt < 2; ++mt) {
            unsigned a[16];
#pragma unroll
            for (int kt = 0; kt < 4; ++kt) {
                a[kt*4+0] = sHu[warp][mt*16 + lq    ][kt*8 + lp    ];
                a[kt*4+1] = sHu[warp][mt*16 + lq + 8][kt*8 + lp    ];
                a[kt*4+2] = sHu[warp][mt*16 + lq    ][kt*8 + lp + 4];
                a[kt*4+3] = sHu[warp][mt*16 + lq + 8][kt*8 + lp + 4];
            }
#pragma unroll
            for (int nt = 0; nt < 4; ++nt) {
                float d0 = 0.0f, d1 = 0.0f, d2 = 0.0f, d3 = 0.0f;
#pragma unroll
                for (int kt = 0; kt < 4; ++kt)
                    mma8(d0, d1, d2, d3,
                         a[kt*4+0], a[kt*4+1], a[kt*4+2], a[kt*4+3],
                         sB0[kt*4+nt][lane], sB1[kt*4+nt][lane]);
                const int c0 = nt*8 + 2*lp;
                const float2 gv = *(const float2*)&sGw[warp][c0];
                const float2 wv = *(const float2*)&sW3s[c0];
                s3p[mt*2+0] = fmaf(fmaxf(d0 + gv.x, 0.0f), wv.x, s3p[mt*2+0]);
                s3p[mt*2+0] = fmaf(fmaxf(d1 + gv.y, 0.0f), wv.y, s3p[mt*2+0]);
                s3p[mt*2+1] = fmaf(fmaxf(d2 + gv.x, 0.0f), wv.x, s3p[mt*2+1]);
                s3p[mt*2+1] = fmaf(fmaxf(d3 + gv.y, 0.0f), wv.y, s3p[mt*2+1]);
            }
        }
#pragma unroll
        for (int k = 0; k < 4; ++k) {
            s3p[k] += __shfl_xor_sync(FULLMASK, s3p[k], 1);
            s3p[k] += __shfl_xor_sync(FULLMASK, s3p[k], 2);
        }
        float wr[4];
#pragma unroll
        for (int k = 0; k < 4; ++k)
            wr[k] = 1.0f / (1.0f + __expf(-(s3p[k] + cB3[0])));
        if (lp == 0) {
            sG[warp][lq     ] = wr[0];
            sG[warp][lq +  8] = wr[1];
            sG[warp][lq + 16] = wr[2];
            sG[warp][lq + 24] = wr[3];
        }
        __syncwarp();
        const float wgt = sG[warp][lane];

        out_weights[i * 32 + lane] = wgt;

        // ---- weighted covariance butterfly; lane 0 stashes sums ----
        float cxx = wgt*dcx*dcx, cxy = wgt*dcx*dcy, cxz = wgt*dcx*dcz;
        float cyy = wgt*dcy*dcy, cyz = wgt*dcy*dcz, czz = wgt*dcz*dcz;
#pragma unroll
        for (int s = 16; s > 0; s >>= 1) {
            cxx += __shfl_xor_sync(FULLMASK, cxx, s);
            cxy += __shfl_xor_sync(FULLMASK, cxy, s);
            cxz += __shfl_xor_sync(FULLMASK, cxz, s);
            cyy += __shfl_xor_sync(FULLMASK, cyy, s);
            cyz += __shfl_xor_sync(FULLMASK, cyz, s);
            czz += __shfl_xor_sync(FULLMASK, czz, s);
        }
        if (lane == 0) {
            const int slot = t * 8 + warp;
            sCov[slot][0] = cxx; sCov[slot][1] = cxy; sCov[slot][2] = cxz;
            sCov[slot][3] = cyy; sCov[slot][4] = cyz; sCov[slot][5] = czz;
        }

        } // i < N
        __syncwarp();
    }

    // ---- batched eigensolve: 32 points of this CTA, lane-parallel on warp 0 ----
    __syncthreads();
    if (warp == 0) {
        const int p = blockIdx.x * 32 + lane;
        if (p < N) {
            const float a00 = sCov[lane][0] + 1e-8f;
            const float a01 = sCov[lane][1];
            const float a02 = sCov[lane][2];
            const float a11 = sCov[lane][3] + 1e-8f;
            const float a12 = sCov[lane][4];
            const float a22 = sCov[lane][5] + 1e-8f;

            const float q = (a00 + a11 + a22) / 3.0f;
            const float b00 = a00 - q, b11 = a11 - q, b22 = a22 - q;
            const float ss = b00*b00 + b11*b11 + b22*b22
                           + 2.0f*(a01*a01 + a02*a02 + a12*a12);
            const float pp = sqrtf(ss / 6.0f) + 1e-20f;

            const float B00 = b00/pp, B11 = b11/pp, B22 = b22/pp;
            const float B01 = a01/pp, B02 = a02/pp, B12 = a12/pp;
            const float det = B00*(B11*B22 - B12*B12)
                            - B01*(B01*B22 - B12*B02)
                            + B02*(B01*B12 - B11*B02);
            float r = det / 2.0f;
            r = fminf(fmaxf(r, -1.0f + 1e-7f), 1.0f - 1e-7f);
            const float phi = acosf(r) / 3.0f;
            const float e1 = q + 2.0f*pp*cosf(phi);
            const float e3 = q + 2.0f*pp*cosf(phi + 2.0943951023931953f);
            const float e2 = 3.0f*q - e1 - e3;

            float lam = e1, ab = fabsf(e1);
            if (fabsf(e2) < ab) { lam = e2; ab = fabsf(e2); }
            if (fabsf(e3) < ab) { lam = e3; }

            const float m00 = a00 - lam, m11 = a11 - lam, m22 = a22 - lam;
            const float c0x = a01*a12 - a02*m11;
            const float c0y = a02*a01 - m00*a12;
            const float c0z = m00*m11 - a01*a01;
            const float c1x = m11*m22 - a12*a12;
            const float c1y = a12*a02 - a01*m22;
            const float c1z = a01*a12 - m11*a02;
            const float c2x = a12*a02 - m22*a01;
            const float c2y = m22*m00 - a02*a02;
            const float c2z = a02*a01 - a12*m00;

            const float n0 = sqrtf(c0x*c0x + c0y*c0y + c0z*c0z);
            const float n1 = sqrtf(c1x*c1x + c1y*c1y + c1z*c1z);
            const float n2 = sqrtf(c2x*c2x + c2y*c2y + c2z*c2z);

            float vx = c0x, vy = c0y, vz = c0z, bn = n0;
            if (n1 > bn) { vx = c1x; vy = c1y; vz = c1z; bn = n1; }
            if (n2 > bn) { vx = c2x; vy = c2y; vz = c2z; }

            const float nv = sqrtf(vx*vx + vy*vy + vz*vz) + 1e-12f;
            out_normals[3*p+0] = vx / nv;
            out_normals[3*p+1] = vy / nv;
            out_normals[3*p+2] = vz / nv;
        }
    }
}

extern "C" void kernel_launch(void* const* d_in, const int* in_sizes, int n_in,
                              void* d_out, int out_size)
{
    const float* old_w   = (const float*)d_in[0];
    const float* pos     = (const float*)d_in[1];
    const float* normals = (const float*)d_in[3];
    const int*   dense_l = (const int*)d_in[5];
    const float* stddev  = (const float*)d_in[6];
    const float* W1      = (const float*)d_in[7];
    const float* b1      = (const float*)d_in[8];
    const float* W2      = (const float*)d_in[9];
    const float* b2      = (const float*)d_in[10];
    const float* W3      = (const float*)d_in[11];
    const float* b3      = (const float*)d_in[12];

    const int N = in_sizes[1] / 3;

    cudaMemcpyToSymbolAsync(cW1, W1, 7 * 32 * sizeof(float), 0, cudaMemcpyDeviceToDevice);
    cudaMemcpyToSymbolAsync(cB1, b1, 32 * sizeof(float),     0, cudaMemcpyDeviceToDevice);
    cudaMemcpyToSymbolAsync(cB2, b2, 32 * sizeof(float),     0, cudaMemcpyDeviceToDevice);
    cudaMemcpyToSymbolAsync(cW3, W3, 32 * sizeof(float),     0, cudaMemcpyDeviceToDevice);
    cudaMemcpyToSymbolAsync(cB3, b3, sizeof(float),          0, cudaMemcpyDeviceToDevice);

    float* out         = (float*)d_out;
    float* out_normals = out;
    float* out_weights = out + (size_t)N * 3;

    pack_kernel<<<(N + 255) / 256, 256>>>(pos, normals, stddev, N);

    const int pts_per_cta = 8 * ITERS;
    dim3 block(256);
    dim3 grid((N + pts_per_cta - 1) / pts_per_cta);
    normal_est_kernel<<<grid, block>>>(old_w, dense_l, W2,
                                       out_normals, out_weights, N);
}

// round 12
// speedup vs baseline: 1.5086x; 1.3363x over previous
#include <cuda_runtime.h>

#define FULLMASK 0xffffffffu
#define ITERS 4   // points per warp; CTA covers 32 points
#define HPAD 20   // half2-words per sHu row (80B, conflict-free for store+Afrag)

// ---- weights in constant memory ----
__constant__ float cW1[7 * 32];
__constant__ float cB1[32];
__constant__ float cB2[32];
__constant__ float cW3[32];
__constant__ float cB3[1];

// ---- packed per-point data: one 32B-aligned record ----
struct __align__(32) PtData { float4 c; float4 n; };
__device__ PtData g_pt[50048];

__global__ __launch_bounds__(256) void pack_kernel(
    const float* __restrict__ pos,
    const float* __restrict__ normals,
    const float* __restrict__ stddev,
    int N)
{
    int i = blockIdx.x * 256 + threadIdx.x;
    if (i >= N) return;
    float4 a, b;
    a.x = pos[3*i+0]; a.y = pos[3*i+1]; a.z = pos[3*i+2]; a.w = stddev[i];
    b.x = normals[3*i+0]; b.y = normals[3*i+1]; b.z = normals[3*i+2]; b.w = 0.0f;
    g_pt[i].c = a;
    g_pt[i].n = b;
}

__device__ __forceinline__ void ldg256(const PtData* p, float4& a, float4& b) {
    asm("ld.global.nc.v8.f32 {%0,%1,%2,%3,%4,%5,%6,%7}, [%8];"
        : "=f"(a.x), "=f"(a.y), "=f"(a.z), "=f"(a.w),
          "=f"(b.x), "=f"(b.y), "=f"(b.z), "=f"(b.w)
        : "l"(p));
}

// pack two fp32 -> f16x2 (lo = first arg)
__device__ __forceinline__ unsigned pack2(float lo, float hi) {
    unsigned r;
    asm("cvt.rn.f16x2.f32 %0, %1, %2;" : "=r"(r) : "f"(hi), "f"(lo));
    return r;
}
__device__ __forceinline__ void unpack2(unsigned v, float& lo, float& hi) {
    asm("{ .reg .f16 l, h; mov.b32 {l, h}, %2; cvt.f32.f16 %0, l; cvt.f32.f16 %1, h; }"
        : "=f"(lo), "=f"(hi) : "r"(v));
}
__device__ __forceinline__ unsigned hmax2(unsigned a, unsigned b) {
    unsigned r; asm("max.f16x2 %0, %1, %2;" : "=r"(r) : "r"(a), "r"(b)); return r;
}
__device__ __forceinline__ void mma16(float& d0, float& d1, float& d2, float& d3,
                                      unsigned a0, unsigned a1, unsigned a2, unsigned a3,
                                      unsigned b0, unsigned b1) {
    asm volatile(
        "mma.sync.aligned.m16n8k16.row.col.f32.f16.f16.f32 "
        "{%0,%1,%2,%3}, {%4,%5,%6,%7}, {%8,%9}, {%0,%1,%2,%3};"
        : "+f"(d0), "+f"(d1), "+f"(d2), "+f"(d3)
        : "r"(a0), "r"(a1), "r"(a2), "r"(a3), "r"(b0), "r"(b1));
}

__global__ __launch_bounds__(256, 4) void normal_est_kernel(
    const float* __restrict__ old_w,    // N*32
    const int*   __restrict__ dense_l,  // N*32
    const float* __restrict__ W2g,      // (64,32)
    float* __restrict__ out_normals,
    float* __restrict__ out_weights,
    int N)
{
    __shared__ unsigned sHu[8][32][HPAD];   // per-warp h rows, f16x2 pairs (16 used)
    __shared__ unsigned sB0h[8][32];        // B frags b0, [kt*4+nt][lane], f16x2
    __shared__ unsigned sB1h[8][32];        // B frags b1
    __shared__ __align__(16) float sW2bT[32][36];   // [j][m] = W2[32+m][j] (fp32 gw path)
    __shared__ __align__(16) float sG[8][32];       // g; reused for wgt redistribution
    __shared__ __align__(8)  float sGw[8][32];
    __shared__            float    sW3s[32];
    __shared__            float    sCov[32][8];

    const int tid  = threadIdx.x;
    const int lane = tid & 31;
    const int warp = tid >> 5;
    const int lp   = lane & 3;      // quad-lane
    const int lq   = lane >> 2;     // quad-row

    for (int idx = tid; idx < 1024; idx += 256) {
        int m = idx >> 5, j = idx & 31;
        sW2bT[j][m] = W2g[(32 + m) * 32 + j];
    }
    // B fragments for m16n8k16 f16 (row.col): frag = kt*4+nt
    // b0 = rows kt*16+{2lp,2lp+1}, col nt*8+lq ; b1 = rows kt*16+8+{2lp,2lp+1}
    {
        const int idx = tid;          // 256 threads = 8 frags x 32 lanes
        const int frag = idx >> 5, l2 = idx & 31;
        const int lp2 = l2 & 3, lq2 = l2 >> 2;
        const int kt = frag >> 2, nt = frag & 3;
        const int n  = nt * 8 + lq2;
        const int k0 = kt * 16 + 2 * lp2;
        sB0h[frag][l2] = pack2(W2g[(k0    ) * 32 + n], W2g[(k0 + 1) * 32 + n]);
        sB1h[frag][l2] = pack2(W2g[(k0 + 8) * 32 + n], W2g[(k0 + 9) * 32 + n]);
    }
    if (tid < 32) sW3s[tid] = cW3[tid];
    __syncthreads();

    for (int t = 0; t < ITERS; ++t) {
        const int i = blockIdx.x * (8 * ITERS) + t * 8 + warp;
        if (i < N) {

        // ---- gather: one 256-bit load per record ----
        const int nb = dense_l[i * 32 + lane];
        float4 ci, ni, cj, nj;
        ldg256(&g_pt[i],  ci, ni);
        ldg256(&g_pt[nb], cj, nj);

        const float dcx = cj.x - ci.x, dcy = cj.y - ci.y, dcz = cj.z - ci.z;
        const float invsd = 1.0f / ci.w;
        const float dx = dcx * invsd, dy = dcy * invsd, dz = dcz * invsd;
        const float wo = old_w[i * 32 + lane];
        const float f4 = fabsf(dx*ni.x + dy*ni.y + dz*ni.z);
        const float f5 = fabsf(dx*nj.x + dy*nj.y + dz*nj.z);
        const float f6 = fabsf(ni.x*nj.x + ni.y*nj.y + ni.z*nj.z);
        float f[7];
        f[0] = dx; f[1] = dy; f[2] = dz; f[3] = wo; f[4] = f4; f[5] = f5; f[6] = f6;

        // ---- layer 1 (constant port), two 16-wide halves; store as f16x2 ----
#pragma unroll
        for (int jh = 0; jh < 2; ++jh) {
            float h[16];
#pragma unroll
            for (int k = 0; k < 16; k += 4) {
                const float4 bv = *(const float4*)&cB1[jh*16 + k];
                h[k+0] = bv.x; h[k+1] = bv.y; h[k+2] = bv.z; h[k+3] = bv.w;
            }
#pragma unroll
            for (int in = 0; in < 7; ++in) {
                const float fv = f[in];
#pragma unroll
                for (int k = 0; k < 16; k += 4) {
                    const float4 wv = *(const float4*)&cW1[in*32 + jh*16 + k];
                    h[k+0] = fmaf(fv, wv.x, h[k+0]);
                    h[k+1] = fmaf(fv, wv.y, h[k+1]);
                    h[k+2] = fmaf(fv, wv.z, h[k+2]);
                    h[k+3] = fmaf(fv, wv.w, h[k+3]);
                }
            }
#pragma unroll
            for (int q = 0; q < 8; ++q)
                sHu[warp][lane][jh*8 + q] =
                    pack2(fmaxf(h[2*q+0], 0.0f), fmaxf(h[2*q+1], 0.0f));
        }
        __syncwarp();

        // ---- segment max over 32 rows, on f16x2 pairs ----
        // lane<16: pair=lane, even rows; lane>=16: pair=lane-16, odd rows
        {
            const int pr = lane & 15;
            const int ro = lane >> 4;            // 0 = even rows, 1 = odd rows
            unsigned m2 = sHu[warp][ro][pr];
#pragma unroll
            for (int k = 1; k < 16; ++k)
                m2 = hmax2(m2, sHu[warp][2*k + ro][pr]);
            const unsigned other =
                __shfl_sync(FULLMASK, m2, pr + ((lane < 16) ? 16 : 0));
            m2 = hmax2(m2, other);
            if (lane < 16) {
                float lo, hi;
                unpack2(m2, lo, hi);
                *(float2*)&sG[warp][2*pr] = make_float2(lo, hi);
            }
        }
        __syncwarp();

        // ---- gw = b2 + g @ W2[32:64] (fp32, once per point) ----
        float gw = cB2[lane];
        {
            const float4* grow = (const float4*)&sG[warp][0];
            const float4* wrow = (const float4*)&sW2bT[lane][0];
#pragma unroll
            for (int q = 0; q < 8; ++q) {
                const float4 gv = grow[q], wv = wrow[q];
                gw = fmaf(gv.x, wv.x, gw); gw = fmaf(gv.y, wv.y, gw);
                gw = fmaf(gv.z, wv.z, gw); gw = fmaf(gv.w, wv.w, gw);
            }
        }
        sGw[warp][lane] = gw;
        __syncwarp();

        // ---- layer 2 on tensor pipe: f16 m16n8k16, K=32 in 2 chunks ----
        float s3p[4] = {0.0f, 0.0f, 0.0f, 0.0f};
#pragma unroll
        for (int mt = 0; mt < 2; ++mt) {
            unsigned a[8];
#pragma unroll
            for (int kt = 0; kt < 2; ++kt) {
                a[kt*4+0] = sHu[warp][mt*16 + lq    ][kt*8 + lp    ];
                a[kt*4+1] = sHu[warp][mt*16 + lq + 8][kt*8 + lp    ];
                a[kt*4+2] = sHu[warp][mt*16 + lq    ][kt*8 + lp + 4];
                a[kt*4+3] = sHu[warp][mt*16 + lq + 8][kt*8 + lp + 4];
            }
#pragma unroll
            for (int nt = 0; nt < 4; ++nt) {
                float d0 = 0.0f, d1 = 0.0f, d2 = 0.0f, d3 = 0.0f;
#pragma unroll
                for (int kt = 0; kt < 2; ++kt)
                    mma16(d0, d1, d2, d3,
                          a[kt*4+0], a[kt*4+1], a[kt*4+2], a[kt*4+3],
                          sB0h[kt*4+nt][lane], sB1h[kt*4+nt][lane]);
                const int c0 = nt*8 + 2*lp;
                const float2 gv = *(const float2*)&sGw[warp][c0];
                const float2 wv = *(const float2*)&sW3s[c0];
                s3p[mt*2+0] = fmaf(fmaxf(d0 + gv.x, 0.0f), wv.x, s3p[mt*2+0]);
                s3p[mt*2+0] = fmaf(fmaxf(d1 + gv.y, 0.0f), wv.y, s3p[mt*2+0]);
                s3p[mt*2+1] = fmaf(fmaxf(d2 + gv.x, 0.0f), wv.x, s3p[mt*2+1]);
                s3p[mt*2+1] = fmaf(fmaxf(d3 + gv.y, 0.0f), wv.y, s3p[mt*2+1]);
            }
        }
#pragma unroll
        for (int k = 0; k < 4; ++k) {
            s3p[k] += __shfl_xor_sync(FULLMASK, s3p[k], 1);
            s3p[k] += __shfl_xor_sync(FULLMASK, s3p[k], 2);
        }
        float wr[4];
#pragma unroll
        for (int k = 0; k < 4; ++k)
            wr[k] = 1.0f / (1.0f + __expf(-(s3p[k] + cB3[0])));
        if (lp == 0) {
            sG[warp][lq     ] = wr[0];
            sG[warp][lq +  8] = wr[1];
            sG[warp][lq + 16] = wr[2];
            sG[warp][lq + 24] = wr[3];
        }
        __syncwarp();
        const float wgt = sG[warp][lane];

        out_weights[i * 32 + lane] = wgt;

        // ---- weighted covariance butterfly; lane 0 stashes sums ----
        float cxx = wgt*dcx*dcx, cxy = wgt*dcx*dcy, cxz = wgt*dcx*dcz;
        float cyy = wgt*dcy*dcy, cyz = wgt*dcy*dcz, czz = wgt*dcz*dcz;
#pragma unroll
        for (int s = 16; s > 0; s >>= 1) {
            cxx += __shfl_xor_sync(FULLMASK, cxx, s);
            cxy += __shfl_xor_sync(FULLMASK, cxy, s);
            cxz += __shfl_xor_sync(FULLMASK, cxz, s);
            cyy += __shfl_xor_sync(FULLMASK, cyy, s);
            cyz += __shfl_xor_sync(FULLMASK, cyz, s);
            czz += __shfl_xor_sync(FULLMASK, czz, s);
        }
        if (lane == 0) {
            const int slot = t * 8 + warp;
            sCov[slot][0] = cxx; sCov[slot][1] = cxy; sCov[slot][2] = cxz;
            sCov[slot][3] = cyy; sCov[slot][4] = cyz; sCov[slot][5] = czz;
        }

        } // i < N
        __syncwarp();
    }

    // ---- batched eigensolve: 32 points, lane-parallel on warp 0 ----
    __syncthreads();
    if (warp == 0) {
        const int p = blockIdx.x * 32 + lane;
        if (p < N) {
            const float a00 = sCov[lane][0] + 1e-8f;
            const float a01 = sCov[lane][1];
            const float a02 = sCov[lane][2];
            const float a11 = sCov[lane][3] + 1e-8f;
            const float a12 = sCov[lane][4];
            const float a22 = sCov[lane][5] + 1e-8f;

            const float q = (a00 + a11 + a22) / 3.0f;
            const float b00 = a00 - q, b11 = a11 - q, b22 = a22 - q;
            const float ss = b00*b00 + b11*b11 + b22*b22
                           + 2.0f*(a01*a01 + a02*a02 + a12*a12);
            const float pp = sqrtf(ss / 6.0f) + 1e-20f;

            const float B00 = b00/pp, B11 = b11/pp, B22 = b22/pp;
            const float B01 = a01/pp, B02 = a02/pp, B12 = a12/pp;
            const float det = B00*(B11*B22 - B12*B12)
                            - B01*(B01*B22 - B12*B02)
                            + B02*(B01*B12 - B11*B02);
            float r = det / 2.0f;
            r = fminf(fmaxf(r, -1.0f + 1e-7f), 1.0f - 1e-7f);
            const float phi = acosf(r) / 3.0f;
            const float e1 = q + 2.0f*pp*cosf(phi);
            const float e3 = q + 2.0f*pp*cosf(phi + 2.0943951023931953f);
            const float e2 = 3.0f*q - e1 - e3;

            float lam = e1, ab = fabsf(e1);
            if (fabsf(e2) < ab) { lam = e2; ab = fabsf(e2); }
            if (fabsf(e3) < ab) { lam = e3; }

            const float m00 = a00 - lam, m11 = a11 - lam, m22 = a22 - lam;
            const float c0x = a01*a12 - a02*m11;
            const float c0y = a02*a01 - m00*a12;
            const float c0z = m00*m11 - a01*a01;
            const float c1x = m11*m22 - a12*a12;
            const float c1y = a12*a02 - a01*m22;
            const float c1z = a01*a12 - m11*a02;
            const float c2x = a12*a02 - m22*a01;
            const float c2y = m22*m00 - a02*a02;
            const float c2z = a02*a01 - a12*m00;

            const float n0 = sqrtf(c0x*c0x + c0y*c0y + c0z*c0z);
            const float n1 = sqrtf(c1x*c1x + c1y*c1y + c1z*c1z);
            const float n2 = sqrtf(c2x*c2x + c2y*c2y + c2z*c2z);

            float vx = c0x, vy = c0y, vz = c0z, bn = n0;
            if (n1 > bn) { vx = c1x; vy = c1y; vz = c1z; bn = n1; }
            if (n2 > bn) { vx = c2x; vy = c2y; vz = c2z; }

            const float nv = sqrtf(vx*vx + vy*vy + vz*vz) + 1e-12f;
            out_normals[3*p+0] = vx / nv;
            out_normals[3*p+1] = vy / nv;
            out_normals[3*p+2] = vz / nv;
        }
    }
}

extern "C" void kernel_launch(void* const* d_in, const int* in_sizes, int n_in,
                              void* d_out, int out_size)
{
    const float* old_w   = (const float*)d_in[0];
    const float* pos     = (const float*)d_in[1];
    const float* normals = (const float*)d_in[3];
    const int*   dense_l = (const int*)d_in[5];
    const float* stddev  = (const float*)d_in[6];
    const float* W1      = (const float*)d_in[7];
    const float* b1      = (const float*)d_in[8];
    const float* W2      = (const float*)d_in[9];
    const float* b2      = (const float*)d_in[10];
    const float* W3      = (const float*)d_in[11];
    const float* b3      = (const float*)d_in[12];

    const int N = in_sizes[1] / 3;

    cudaMemcpyToSymbolAsync(cW1, W1, 7 * 32 * sizeof(float), 0, cudaMemcpyDeviceToDevice);
    cudaMemcpyToSymbolAsync(cB1, b1, 32 * sizeof(float),     0, cudaMemcpyDeviceToDevice);
    cudaMemcpyToSymbolAsync(cB2, b2, 32 * sizeof(float),     0, cudaMemcpyDeviceToDevice);
    cudaMemcpyToSymbolAsync(cW3, W3, 32 * sizeof(float),     0, cudaMemcpyDeviceToDevice);
    cudaMemcpyToSymbolAsync(cB3, b3, sizeof(float),          0, cudaMemcpyDeviceToDevice);

    float* out         = (float*)d_out;
    float* out_normals = out;
    float* out_weights = out + (size_t)N * 3;

    pack_kernel<<<(N + 255) / 256, 256>>>(pos, normals, stddev, N);

    const int pts_per_cta = 8 * ITERS;
    dim3 block(256);
    dim3 grid((N + pts_per_cta - 1) / pts_per_cta);
    normal_est_kernel<<<grid, block>>>(old_w, dense_l, W2,
                                       out_normals, out_weights, N);
}

// round 13
// speedup vs baseline: 1.5554x; 1.0310x over previous
#include <cuda_runtime.h>

#define FULLMASK 0xffffffffu
#define ITERS 4   // points per warp; CTA covers 32 points
#define HPAD 20   // half2-words per sHu row (80B, conflict-free)

// ---- weights in constant memory ----
__constant__ float cW1[7 * 32];
__constant__ float cB1[32];
__constant__ float cB2[32];
__constant__ float cW3[32];
__constant__ float cB3[1];

// ---- packed per-point data: one 32B-aligned record ----
struct __align__(32) PtData { float4 c; float4 n; };
__device__ PtData g_pt[50048];

__global__ __launch_bounds__(256) void pack_kernel(
    const float* __restrict__ pos,
    const float* __restrict__ normals,
    const float* __restrict__ stddev,
    int N)
{
    int i = blockIdx.x * 256 + threadIdx.x;
    if (i >= N) return;
    float4 a, b;
    a.x = pos[3*i+0]; a.y = pos[3*i+1]; a.z = pos[3*i+2]; a.w = stddev[i];
    b.x = normals[3*i+0]; b.y = normals[3*i+1]; b.z = normals[3*i+2]; b.w = 0.0f;
    g_pt[i].c = a;
    g_pt[i].n = b;
}

__device__ __forceinline__ void ldg256(const PtData* p, float4& a, float4& b) {
    asm("ld.global.nc.v8.f32 {%0,%1,%2,%3,%4,%5,%6,%7}, [%8];"
        : "=f"(a.x), "=f"(a.y), "=f"(a.z), "=f"(a.w),
          "=f"(b.x), "=f"(b.y), "=f"(b.z), "=f"(b.w)
        : "l"(p));
}

__device__ __forceinline__ unsigned pack2(float lo, float hi) {
    unsigned r;
    asm("cvt.rn.f16x2.f32 %0, %1, %2;" : "=r"(r) : "f"(hi), "f"(lo));
    return r;
}
__device__ __forceinline__ unsigned hmax2(unsigned a, unsigned b) {
    unsigned r; asm("max.f16x2 %0, %1, %2;" : "=r"(r) : "r"(a), "r"(b)); return r;
}
__device__ __forceinline__ void mma16(float& d0, float& d1, float& d2, float& d3,
                                      unsigned a0, unsigned a1, unsigned a2, unsigned a3,
                                      unsigned b0, unsigned b1) {
    asm volatile(
        "mma.sync.aligned.m16n8k16.row.col.f32.f16.f16.f32 "
        "{%0,%1,%2,%3}, {%4,%5,%6,%7}, {%8,%9}, {%0,%1,%2,%3};"
        : "+f"(d0), "+f"(d1), "+f"(d2), "+f"(d3)
        : "r"(a0), "r"(a1), "r"(a2), "r"(a3), "r"(b0), "r"(b1));
}

__global__ __launch_bounds__(256, 4) void normal_est_kernel(
    const float* __restrict__ old_w,    // N*32
    const int*   __restrict__ dense_l,  // N*32
    const float* __restrict__ W2g,      // (64,32)
    float* __restrict__ out_normals,
    float* __restrict__ out_weights,
    int N)
{
    __shared__ unsigned sHu[8][32][HPAD];   // per-warp h rows, f16x2 (16 used)
    __shared__ unsigned sB0h[16][32];       // B frags b0, [kt*4+nt][lane], f16x2  (K=64)
    __shared__ unsigned sB1h[16][32];       // B frags b1
    __shared__ unsigned sGh[8][16];         // per-warp g as f16x2 pairs
    __shared__ __align__(16) float sG[8][32];   // wgt redistribution
    __shared__ __align__(16) float sEp[64];     // interleaved [b2[j], W3[j]]
    __shared__            float    sCov[32][8];

    const int tid  = threadIdx.x;
    const int lane = tid & 31;
    const int warp = tid >> 5;
    const int lp   = lane & 3;      // quad-lane
    const int lq   = lane >> 2;     // quad-row

    // B fragments for m16n8k16 f16 (row.col), full K=64 of W2
    for (int it = tid; it < 512; it += 256) {
        const int frag = it >> 5, l2 = it & 31;
        const int lp2 = l2 & 3, lq2 = l2 >> 2;
        const int kt = frag >> 2, nt = frag & 3;
        const int n  = nt * 8 + lq2;
        const int k0 = kt * 16 + 2 * lp2;
        sB0h[frag][l2] = pack2(W2g[(k0    ) * 32 + n], W2g[(k0 + 1) * 32 + n]);
        sB1h[frag][l2] = pack2(W2g[(k0 + 8) * 32 + n], W2g[(k0 + 9) * 32 + n]);
    }
    if (tid < 32) { sEp[2*tid] = cB2[tid]; sEp[2*tid+1] = cW3[tid]; }
    __syncthreads();

    for (int t = 0; t < ITERS; ++t) {
        const int i = blockIdx.x * (8 * ITERS) + t * 8 + warp;
        if (i < N) {

        // ---- gather: one 256-bit load per record ----
        const int nb = dense_l[i * 32 + lane];
        float4 ci, ni, cj, nj;
        ldg256(&g_pt[i],  ci, ni);
        ldg256(&g_pt[nb], cj, nj);

        const float dcx = cj.x - ci.x, dcy = cj.y - ci.y, dcz = cj.z - ci.z;
        const float invsd = 1.0f / ci.w;
        const float dx = dcx * invsd, dy = dcy * invsd, dz = dcz * invsd;
        const float wo = old_w[i * 32 + lane];
        const float f4 = fabsf(dx*ni.x + dy*ni.y + dz*ni.z);
        const float f5 = fabsf(dx*nj.x + dy*nj.y + dz*nj.z);
        const float f6 = fabsf(ni.x*nj.x + ni.y*nj.y + ni.z*nj.z);
        float f[7];
        f[0] = dx; f[1] = dy; f[2] = dz; f[3] = wo; f[4] = f4; f[5] = f5; f[6] = f6;

        // ---- layer 1 (constant port), two 16-wide halves; store f16x2 ----
#pragma unroll
        for (int jh = 0; jh < 2; ++jh) {
            float h[16];
#pragma unroll
            for (int k = 0; k < 16; k += 4) {
                const float4 bv = *(const float4*)&cB1[jh*16 + k];
                h[k+0] = bv.x; h[k+1] = bv.y; h[k+2] = bv.z; h[k+3] = bv.w;
            }
#pragma unroll
            for (int in = 0; in < 7; ++in) {
                const float fv = f[in];
#pragma unroll
                for (int k = 0; k < 16; k += 4) {
                    const float4 wv = *(const float4*)&cW1[in*32 + jh*16 + k];
                    h[k+0] = fmaf(fv, wv.x, h[k+0]);
                    h[k+1] = fmaf(fv, wv.y, h[k+1]);
                    h[k+2] = fmaf(fv, wv.z, h[k+2]);
                    h[k+3] = fmaf(fv, wv.w, h[k+3]);
                }
            }
#pragma unroll
            for (int q = 0; q < 8; ++q)
                sHu[warp][lane][jh*8 + q] =
                    pack2(fmaxf(h[2*q+0], 0.0f), fmaxf(h[2*q+1], 0.0f));
        }
        __syncwarp();

        // ---- segment max over 32 rows (f16x2); store g pairs to sGh ----
        {
            const int pr = lane & 15;
            const int ro = lane >> 4;
            unsigned m2 = sHu[warp][ro][pr];
#pragma unroll
            for (int k = 1; k < 16; ++k)
                m2 = hmax2(m2, sHu[warp][2*k + ro][pr]);
            const unsigned other =
                __shfl_sync(FULLMASK, m2, pr + ((lane < 16) ? 16 : 0));
            m2 = hmax2(m2, other);
            if (lane < 16) sGh[warp][pr] = m2;
        }
        __syncwarp();

        // ---- A fragments: h (16 regs) + g broadcast (4 regs) ----
        unsigned ah[16];
#pragma unroll
        for (int mt = 0; mt < 2; ++mt)
#pragma unroll
            for (int kt = 0; kt < 2; ++kt) {
                unsigned* a = &ah[(mt*2+kt)*4];
                a[0] = sHu[warp][mt*16 + lq    ][kt*8 + lp    ];
                a[1] = sHu[warp][mt*16 + lq + 8][kt*8 + lp    ];
                a[2] = sHu[warp][mt*16 + lq    ][kt*8 + lp + 4];
                a[3] = sHu[warp][mt*16 + lq + 8][kt*8 + lp + 4];
            }
        unsigned ga[4];
        ga[0] = sGh[warp][lp];      ga[1] = sGh[warp][lp + 4];
        ga[2] = sGh[warp][lp + 8];  ga[3] = sGh[warp][lp + 12];

        // ---- layer 2 fused (K=64: h @ W2a + g @ W2b), f16 mma ----
        float s3p[4] = {0.0f, 0.0f, 0.0f, 0.0f};
#pragma unroll
        for (int nt = 0; nt < 4; ++nt) {
            float d[8] = {0,0,0,0,0,0,0,0};
#pragma unroll
            for (int kt = 0; kt < 2; ++kt) {
                const unsigned b0 = sB0h[kt*4+nt][lane];
                const unsigned b1 = sB1h[kt*4+nt][lane];
                const unsigned* a0 = &ah[(0*2+kt)*4];
                const unsigned* a1 = &ah[(1*2+kt)*4];
                mma16(d[0], d[1], d[2], d[3], a0[0], a0[1], a0[2], a0[3], b0, b1);
                mma16(d[4], d[5], d[6], d[7], a1[0], a1[1], a1[2], a1[3], b0, b1);
            }
#pragma unroll
            for (int kt = 2; kt < 4; ++kt) {
                const unsigned b0 = sB0h[kt*4+nt][lane];
                const unsigned b1 = sB1h[kt*4+nt][lane];
                const unsigned g0 = ga[(kt-2)*2+0];
                const unsigned g1 = ga[(kt-2)*2+1];
                mma16(d[0], d[1], d[2], d[3], g0, g0, g1, g1, b0, b1);
                mma16(d[4], d[5], d[6], d[7], g0, g0, g1, g1, b0, b1);
            }
            const int c0 = nt*8 + 2*lp;
            const float4 ep = *(const float4*)&sEp[2*c0];  // b2[c0],w3[c0],b2[c0+1],w3[c0+1]
            s3p[0] = fmaf(fmaxf(d[0] + ep.x, 0.0f), ep.y, s3p[0]);
            s3p[0] = fmaf(fmaxf(d[1] + ep.z, 0.0f), ep.w, s3p[0]);
            s3p[1] = fmaf(fmaxf(d[2] + ep.x, 0.0f), ep.y, s3p[1]);
            s3p[1] = fmaf(fmaxf(d[3] + ep.z, 0.0f), ep.w, s3p[1]);
            s3p[2] = fmaf(fmaxf(d[4] + ep.x, 0.0f), ep.y, s3p[2]);
            s3p[2] = fmaf(fmaxf(d[5] + ep.z, 0.0f), ep.w, s3p[2]);
            s3p[3] = fmaf(fmaxf(d[6] + ep.x, 0.0f), ep.y, s3p[3]);
            s3p[3] = fmaf(fmaxf(d[7] + ep.z, 0.0f), ep.w, s3p[3]);
        }
#pragma unroll
        for (int k = 0; k < 4; ++k) {
            s3p[k] += __shfl_xor_sync(FULLMASK, s3p[k], 1);
            s3p[k] += __shfl_xor_sync(FULLMASK, s3p[k], 2);
        }
        float wr[4];
#pragma unroll
        for (int k = 0; k < 4; ++k)
            wr[k] = 1.0f / (1.0f + __expf(-(s3p[k] + cB3[0])));
        if (lp == 0) {
            sG[warp][lq     ] = wr[0];
            sG[warp][lq +  8] = wr[1];
            sG[warp][lq + 16] = wr[2];
            sG[warp][lq + 24] = wr[3];
        }
        __syncwarp();
        const float wgt = sG[warp][lane];

        out_weights[i * 32 + lane] = wgt;

        // ---- weighted covariance butterfly; lane 0 stashes sums ----
        float cxx = wgt*dcx*dcx, cxy = wgt*dcx*dcy, cxz = wgt*dcx*dcz;
        float cyy = wgt*dcy*dcy, cyz = wgt*dcy*dcz, czz = wgt*dcz*dcz;
#pragma unroll
        for (int s = 16; s > 0; s >>= 1) {
            cxx += __shfl_xor_sync(FULLMASK, cxx, s);
            cxy += __shfl_xor_sync(FULLMASK, cxy, s);
            cxz += __shfl_xor_sync(FULLMASK, cxz, s);
            cyy += __shfl_xor_sync(FULLMASK, cyy, s);
            cyz += __shfl_xor_sync(FULLMASK, cyz, s);
            czz += __shfl_xor_sync(FULLMASK, czz, s);
        }
        if (lane == 0) {
            const int slot = t * 8 + warp;
            sCov[slot][0] = cxx; sCov[slot][1] = cxy; sCov[slot][2] = cxz;
            sCov[slot][3] = cyy; sCov[slot][4] = cyz; sCov[slot][5] = czz;
        }

        } // i < N
        __syncwarp();
    }

    // ---- batched eigensolve: 32 points, lane-parallel on warp 0 ----
    __syncthreads();
    if (warp == 0) {
        const int p = blockIdx.x * 32 + lane;
        if (p < N) {
            const float a00 = sCov[lane][0] + 1e-8f;
            const float a01 = sCov[lane][1];
            const float a02 = sCov[lane][2];
            const float a11 = sCov[lane][3] + 1e-8f;
            const float a12 = sCov[lane][4];
            const float a22 = sCov[lane][5] + 1e-8f;

            const float q = (a00 + a11 + a22) / 3.0f;
            const float b00 = a00 - q, b11 = a11 - q, b22 = a22 - q;
            const float ss = b00*b00 + b11*b11 + b22*b22
                           + 2.0f*(a01*a01 + a02*a02 + a12*a12);
            const float pp = sqrtf(ss / 6.0f) + 1e-20f;

            const float B00 = b00/pp, B11 = b11/pp, B22 = b22/pp;
            const float B01 = a01/pp, B02 = a02/pp, B12 = a12/pp;
            const float det = B00*(B11*B22 - B12*B12)
                            - B01*(B01*B22 - B12*B02)
                            + B02*(B01*B12 - B11*B02);
            float r = det / 2.0f;
            r = fminf(fmaxf(r, -1.0f + 1e-7f), 1.0f - 1e-7f);
            const float phi = acosf(r) / 3.0f;
            const float e1 = q + 2.0f*pp*cosf(phi);
            const float e3 = q + 2.0f*pp*cosf(phi + 2.0943951023931953f);
            const float e2 = 3.0f*q - e1 - e3;

            float lam = e1, ab = fabsf(e1);
            if (fabsf(e2) < ab) { lam = e2; ab = fabsf(e2); }
            if (fabsf(e3) < ab) { lam = e3; }

            const float m00 = a00 - lam, m11 = a11 - lam, m22 = a22 - lam;
            const float c0x = a01*a12 - a02*m11;
            const float c0y = a02*a01 - m00*a12;
            const float c0z = m00*m11 - a01*a01;
            const float c1x = m11*m22 - a12*a12;
            const float c1y = a12*a02 - a01*m22;
            const float c1z = a01*a12 - m11*a02;
            const float c2x = a12*a02 - m22*a01;
            const float c2y = m22*m00 - a02*a02;
            const float c2z = a02*a01 - a12*m00;

            const float n0 = sqrtf(c0x*c0x + c0y*c0y + c0z*c0z);
            const float n1 = sqrtf(c1x*c1x + c1y*c1y + c1z*c1z);
            const float n2 = sqrtf(c2x*c2x + c2y*c2y + c2z*c2z);

            float vx = c0x, vy = c0y, vz = c0z, bn = n0;
            if (n1 > bn) { vx = c1x; vy = c1y; vz = c1z; bn = n1; }
            if (n2 > bn) { vx = c2x; vy = c2y; vz = c2z; }

            const float nv = sqrtf(vx*vx + vy*vy + vz*vz) + 1e-12f;
            out_normals[3*p+0] = vx / nv;
            out_normals[3*p+1] = vy / nv;
            out_normals[3*p+2] = vz / nv;
        }
    }
}

extern "C" void kernel_launch(void* const* d_in, const int* in_sizes, int n_in,
                              void* d_out, int out_size)
{
    const float* old_w   = (const float*)d_in[0];
    const float* pos     = (const float*)d_in[1];
    const float* normals = (const float*)d_in[3];
    const int*   dense_l = (const int*)d_in[5];
    const float* stddev  = (const float*)d_in[6];
    const float* W1      = (const float*)d_in[7];
    const float* b1      = (const float*)d_in[8];
    const float* W2      = (const float*)d_in[9];
    const float* b2      = (const float*)d_in[10];
    const float* W3      = (const float*)d_in[11];
    const float* b3      = (const float*)d_in[12];

    const int N = in_sizes[1] / 3;

    cudaMemcpyToSymbolAsync(cW1, W1, 7 * 32 * sizeof(float), 0, cudaMemcpyDeviceToDevice);
    cudaMemcpyToSymbolAsync(cB1, b1, 32 * sizeof(float),     0, cudaMemcpyDeviceToDevice);
    cudaMemcpyToSymbolAsync(cB2, b2, 32 * sizeof(float),     0, cudaMemcpyDeviceToDevice);
    cudaMemcpyToSymbolAsync(cW3, W3, 32 * sizeof(float),     0, cudaMemcpyDeviceToDevice);
    cudaMemcpyToSymbolAsync(cB3, b3, sizeof(float),          0, cudaMemcpyDeviceToDevice);

    float* out         = (float*)d_out;
    float* out_normals = out;
    float* out_weights = out + (size_t)N * 3;

    pack_kernel<<<(N + 255) / 256, 256>>>(pos, normals, stddev, N);

    const int pts_per_cta = 8 * ITERS;
    dim3 block(256);
    dim3 grid((N + pts_per_cta - 1) / pts_per_cta);
    normal_est_kernel<<<grid, block>>>(old_w, dense_l, W2,
                                       out_normals, out_weights, N);
}